// round 5
// baseline (speedup 1.0000x reference)
#include <cuda_runtime.h>
#include <math.h>

#define BB 64
#define JJ 32
#define NV 4096
#define QD 130
#define KD 128
#define VD 130
#define HH 4
#define QROWS 128              // J*H rows of q per batch
#define OSTRIDE 132            // obuf row stride (130 vals + denom @130 + pad)
// fold log2(e)/sqrt(128) into q so p = exp2f(score)
#define QSCALE (1.4426950408889634f / 11.313708498984761f)

// ---------------- device scratch (static: no runtime allocation) ----------
__device__ float g_qT[BB * KD * QROWS];            // [b][d][qi]  (transposed, scaled)
__device__ float g_P[(size_t)BB * QROWS * NV];     // [b][qi][n]  un-normalized probs
__device__ float g_obuf[BB * QROWS * OSTRIDE];     // [b][qi][132]: 0..129 = P@V, 130 = denom
__device__ float g_keep[BB * NV];                  // 1.0 keep / 0.0 masked
__device__ int   g_maskType;                       // 0=u8 1=i32 2=f32 3=bf16

// ---------------- mask dtype detection (deterministic, data-driven) -------
__global__ void classify_mask(const unsigned char* __restrict__ m, int nbytes) {
    __shared__ int f3Fmod1, f3Fany, fNzOff;
    int tid = threadIdx.x;
    if (tid == 0) { f3Fmod1 = 0; f3Fany = 0; fNzOff = 0; }
    __syncthreads();
    int l0 = 0, l1 = 0, l2 = 0;
    for (int i = tid; i < nbytes; i += blockDim.x) {
        unsigned char v = m[i];
        if (v) {
            if (v == 0x3F) { l1 = 1; if ((i & 3) == 1) l0 = 1; }
            if ((i & 3) != 0) l2 = 1;
        }
    }
    if (l0) atomicOr(&f3Fmod1, 1);
    if (l1) atomicOr(&f3Fany, 1);
    if (l2) atomicOr(&fNzOff, 1);
    __syncthreads();
    if (tid == 0) {
        int t;
        if (f3Fmod1)      t = 3;  // bf16 1.0 = 0x3F80 -> 0x3F at odd byte offsets
        else if (f3Fany)  t = 2;  // f32 1.0 = 0x3F800000 -> 0x3F only at i%4==3
        else if (fNzOff)  t = 0;  // raw bool/u8 bytes
        else              t = 1;  // i32 0/1 (nonzero only at i%4==0)
        g_maskType = t;
    }
}

__global__ void convert_mask(const void* __restrict__ m, int n) {
    int i = blockIdx.x * blockDim.x + threadIdx.x;
    if (i >= n) return;
    int t = g_maskType;
    bool masked;
    if (t == 0)      masked = ((const unsigned char*)m)[i]  != 0;
    else if (t == 1) masked = ((const int*)m)[i]            != 0;
    else if (t == 2) masked = ((const float*)m)[i]          != 0.0f;
    else             masked = ((const unsigned short*)m)[i] != 0;
    g_keep[i] = masked ? 0.0f : 1.0f;
}

__global__ void zero_obuf() {
    int i = blockIdx.x * blockDim.x + threadIdx.x;
    if (i < BB * QROWS * OSTRIDE) g_obuf[i] = 0.0f;
}

// ---------------- kernel A: q encoder MLP, write scaled+transposed q ------
__global__ void __launch_bounds__(128) encoder_kernel(
    const float* __restrict__ jq,
    const float* __restrict__ W1, const float* __restrict__ b1,
    const float* __restrict__ W2, const float* __restrict__ b2) {
    __shared__ float xs[QD];
    __shared__ float hs[64];
    int bid = blockIdx.x;            // b*32 + j
    int b = bid >> 5, j = bid & 31;
    int tid = threadIdx.x;
    for (int i = tid; i < QD; i += 128) xs[i] = jq[(size_t)bid * QD + i];
    __syncthreads();
    if (tid < 64) {
        float s = b1[tid];
        for (int r = 0; r < QD; r++) s += xs[r] * W1[r * 64 + tid];
        hs[tid] = fmaxf(s, 0.0f);
    }
    __syncthreads();
    int k0 = tid * 4;
    float s[4];
    s[0] = b2[k0]; s[1] = b2[k0 + 1]; s[2] = b2[k0 + 2]; s[3] = b2[k0 + 3];
    for (int r = 0; r < 64; r++) {
        float hv = hs[r];
        float4 w = *(const float4*)(W2 + r * 512 + k0);
        s[0] += hv * w.x; s[1] += hv * w.y; s[2] += hv * w.z; s[3] += hv * w.w;
    }
#pragma unroll
    for (int u = 0; u < 4; u++) {
        int k = k0 + u;
        int head = k >> 7, d = k & 127;
        int qi = j * 4 + head;
        g_qT[(b * KD + d) * QROWS + qi] = s[u] * QSCALE;
    }
}

// ---------------- kernel B1: P = exp2(qT K^T) * keep ----------------------
// grid (64 ntiles, 64 b), 256 threads. Per block: all 128 q rows x 64 keys.
// Thread micro-tile: 8q x 4k = 32 fp32 accumulators.
__global__ void __launch_bounds__(256) qk_kernel(const float* __restrict__ Kg) {
    extern __shared__ float sm[];
    float* Qs = sm;                    // [128 d][128 q]
    float* Ks = sm + 128 * 128;        // [128 d][64 n] (transposed)
    float* kp = Ks + 128 * 64;         // keep[64]
    int b = blockIdx.y;
    int n0 = blockIdx.x * 64;
    int tid = threadIdx.x;

    { // Q: straight vector copy (already stored [d][q])
        const float4* src = (const float4*)(g_qT + b * KD * QROWS);
        float4* dst = (float4*)Qs;
#pragma unroll
        for (int i = 0; i < 16; i++) dst[tid + 256 * i] = src[tid + 256 * i];
    }
    { // K: load [n][d] coalesced, store transposed [d][n]
        int n = tid >> 2;
        int dg = (tid & 3) * 32;
        const float* kr = Kg + ((size_t)b * NV + n0 + n) * KD + dg;
#pragma unroll
        for (int u = 0; u < 8; u++) {
            float4 v = *(const float4*)(kr + u * 4);
            int d = dg + u * 4;
            Ks[(d + 0) * 64 + n] = v.x;
            Ks[(d + 1) * 64 + n] = v.y;
            Ks[(d + 2) * 64 + n] = v.z;
            Ks[(d + 3) * 64 + n] = v.w;
        }
    }
    if (tid < 64) kp[tid] = g_keep[b * NV + n0 + tid];
    __syncthreads();

    int kg = tid & 15;      // 4 keys: kg*4..kg*4+3
    int qg = tid >> 4;      // 8 q rows: qg*8..qg*8+7
    float acc[8][4];
#pragma unroll
    for (int i = 0; i < 8; i++)
#pragma unroll
        for (int u = 0; u < 4; u++) acc[i][u] = 0.0f;

    const float* qb = Qs + qg * 8;
    const float* kb = Ks + kg * 4;
#pragma unroll 4
    for (int d = 0; d < 128; d++) {
        float4 k4 = *(const float4*)(kb + d * 64);
        float4 qa = *(const float4*)(qb + d * 128);
        float4 qc = *(const float4*)(qb + d * 128 + 4);
        float qv[8] = {qa.x, qa.y, qa.z, qa.w, qc.x, qc.y, qc.z, qc.w};
        float kv[4] = {k4.x, k4.y, k4.z, k4.w};
#pragma unroll
        for (int i = 0; i < 8; i++)
#pragma unroll
            for (int u = 0; u < 4; u++) acc[i][u] += qv[i] * kv[u];
    }

    float c0 = kp[kg * 4], c1 = kp[kg * 4 + 1], c2 = kp[kg * 4 + 2], c3 = kp[kg * 4 + 3];
#pragma unroll
    for (int i = 0; i < 8; i++) {
        float4 p;
        p.x = exp2f(acc[i][0]) * c0;
        p.y = exp2f(acc[i][1]) * c1;
        p.z = exp2f(acc[i][2]) * c2;
        p.w = exp2f(acc[i][3]) * c3;
        int q = qg * 8 + i;
        *(float4*)(g_P + ((size_t)b * QROWS + q) * NV + n0 + kg * 4) = p;
    }
}

// ---------------- kernel B2: obuf += P @ [V | 1] ---------------------------
// grid (16 = 2 qtiles x 8 nchunks, 64 b), 256 threads.
// Thread micro-tile: 8q x 5v (v = vg + 32m), Vs padded to stride 160 -> conflict-free.
__global__ void __launch_bounds__(256) pv_kernel(const float* __restrict__ Vg) {
    __shared__ float Ps[64 * 32];
    __shared__ float Vs[32 * 160];
    int b = blockIdx.y;
    int qt = blockIdx.x & 1;
    int nc = blockIdx.x >> 1;        // 0..7
    int q0 = qt * 64;
    int nbase = nc * 512;
    int tid = threadIdx.x;
    int qg = tid >> 5;               // 8 groups of 8 q rows
    int vg = tid & 31;

    float acc[8][5];
#pragma unroll
    for (int i = 0; i < 8; i++)
#pragma unroll
        for (int m = 0; m < 5; m++) acc[i][m] = 0.0f;

    for (int ns = 0; ns < 512; ns += 32) {
        __syncthreads();
#pragma unroll
        for (int rr = 0; rr < 2; rr++) {
            int r = (tid >> 3) + rr * 32;
            int c4 = (tid & 7) * 4;
            *(float4*)&Ps[r * 32 + c4] =
                *(const float4*)(g_P + ((size_t)b * QROWS + q0 + r) * NV + nbase + ns + c4);
        }
#pragma unroll
        for (int it = 0; it < 20; it++) {
            int idx = tid + it * 256;
            int n = idx / 160, d = idx - n * 160;
            float val = 0.0f;
            if (d < VD)       val = Vg[((size_t)b * NV + nbase + ns + n) * VD + d];
            else if (d == VD) val = 1.0f;   // ones column -> denominator
            Vs[idx] = val;
        }
        __syncthreads();
#pragma unroll 4
        for (int n = 0; n < 32; n++) {
            float p[8];
#pragma unroll
            for (int i = 0; i < 8; i++) p[i] = Ps[(qg * 8 + i) * 32 + n];
#pragma unroll
            for (int m = 0; m < 5; m++) {
                float v = Vs[n * 160 + vg + 32 * m];
#pragma unroll
                for (int i = 0; i < 8; i++) acc[i][m] += p[i] * v;
            }
        }
    }
#pragma unroll
    for (int i = 0; i < 8; i++) {
        int q = q0 + qg * 8 + i;
        float* orow = g_obuf + ((size_t)b * QROWS + q) * OSTRIDE;
#pragma unroll
        for (int m = 0; m < 5; m++) {
            int d = vg + 32 * m;
            if (d <= VD) atomicAdd(orow + d, acc[i][m]);
        }
    }
}

// ---------------- kernel C: normalize + output MLP -------------------------
__global__ void __launch_bounds__(64) mlp_kernel(
    const float* __restrict__ W3, const float* __restrict__ b3,
    const float* __restrict__ W4, const float* __restrict__ b4,
    const float* __restrict__ W5, const float* __restrict__ b5,
    float* __restrict__ out) {
    __shared__ float os[520];
    __shared__ float h1[64];
    __shared__ float h2[32];
    int bid = blockIdx.x;            // b*32 + j
    int b = bid >> 5, j = bid & 31;
    int tid = threadIdx.x;           // 64
    for (int idx = tid; idx < 520; idx += 64) {
        int h = idx / 130, v = idx - h * 130;
        const float* orow = g_obuf + ((size_t)b * QROWS + j * 4 + h) * OSTRIDE;
        os[idx] = orow[v] / orow[130];
    }
    __syncthreads();
    {
        float s = b3[tid];
        for (int r = 0; r < 520; r++) s += os[r] * W3[r * 64 + tid];
        h1[tid] = fmaxf(s, 0.0f);
    }
    __syncthreads();
    if (tid < 32) {
        float s = b4[tid];
#pragma unroll
        for (int r = 0; r < 64; r++) s += h1[r] * W4[r * 32 + tid];
        h2[tid] = fmaxf(s, 0.0f);
    }
    __syncthreads();
    if (tid < 32) {
        float v = h2[tid] * W5[tid];
#pragma unroll
        for (int off = 16; off; off >>= 1) v += __shfl_down_sync(0xffffffffu, v, off);
        if (tid == 0) out[bid] = v + b5[0];
    }
}

// ---------------- launch ----------------------------------------------------
extern "C" void kernel_launch(void* const* d_in, const int* in_sizes, int n_in,
                              void* d_out, int out_size) {
    const float* jq = (const float*)d_in[0];
    const float* Kg = (const float*)d_in[1];
    const float* Vg = (const float*)d_in[2];
    const void*  mk = d_in[3];
    const float* W1 = (const float*)d_in[4];
    const float* b1 = (const float*)d_in[5];
    const float* W2 = (const float*)d_in[6];
    const float* b2 = (const float*)d_in[7];
    const float* W3 = (const float*)d_in[8];
    const float* b3 = (const float*)d_in[9];
    const float* W4 = (const float*)d_in[10];
    const float* b4 = (const float*)d_in[11];
    const float* W5 = (const float*)d_in[12];
    const float* b5 = (const float*)d_in[13];
    float* out = (float*)d_out;

    classify_mask<<<1, 256>>>((const unsigned char*)mk, BB * NV);
    convert_mask<<<(BB * NV + 255) / 256, 256>>>(mk, BB * NV);
    zero_obuf<<<(BB * QROWS * OSTRIDE + 255) / 256, 256>>>();
    encoder_kernel<<<BB * JJ, 128>>>(jq, W1, b1, W2, b2);

    int smem_b1 = (128 * 128 + 128 * 64 + 64) * (int)sizeof(float);  // 98,560 B
    cudaFuncSetAttribute(qk_kernel, cudaFuncAttributeMaxDynamicSharedMemorySize, smem_b1);
    dim3 g1(NV / 64, BB);
    qk_kernel<<<g1, 256, smem_b1>>>(Kg);

    dim3 g2(16, BB);
    pv_kernel<<<g2, 256>>>(Vg);

    mlp_kernel<<<BB * JJ, 64>>>(W3, b3, W4, b4, W5, b5, out);
}

// round 6
// speedup vs baseline: 1.2253x; 1.2253x over previous
#include <cuda_runtime.h>
#include <cuda_bf16.h>
#include <math.h>

#define BB 64
#define JJ 32
#define NV 4096
#define QD 130
#define KD 128
#define VD 130
#define HH 4
#define QROWS 128              // J*H rows of q per batch
#define OST 136                // obuf row stride (130 vals + denom @130 + pad to n8)
#define NSPLIT 4               // PV n-splits (obuf slots)
// fold log2(e)/sqrt(128) into q so p = exp2f(score)
#define QSCALE (1.4426950408889634f / 11.313708498984761f)

// ---------------- device scratch (static: no runtime allocation) ----------
__device__ __nv_bfloat16 g_Qh[BB * QROWS * KD];    // [b][q][d] hi
__device__ __nv_bfloat16 g_Ql[BB * QROWS * KD];    // [b][q][d] lo
__device__ unsigned g_Ph32[(size_t)BB * QROWS * (NV / 2)];  // packed bf16x2 P hi
__device__ unsigned g_Pl32[(size_t)BB * QROWS * (NV / 2)];  // packed bf16x2 P lo
__device__ float g_obuf2[(size_t)NSPLIT * BB * QROWS * OST];
__device__ float g_keep[BB * NV];                  // 1.0 keep / 0.0 masked
__device__ int   g_maskType;

// bf16 split-pack: two floats -> (hi pair, lo pair) packed u32
__device__ __forceinline__ void splitpack(float x, float y, unsigned& hi, unsigned& lo) {
    __nv_bfloat16 hx = __float2bfloat16(x);
    __nv_bfloat16 hy = __float2bfloat16(y);
    float rx = x - __bfloat162float(hx);
    float ry = y - __bfloat162float(hy);
    hi = (unsigned)__bfloat16_as_ushort(hx) | ((unsigned)__bfloat16_as_ushort(hy) << 16);
    lo = (unsigned)__bfloat16_as_ushort(__float2bfloat16(rx))
       | ((unsigned)__bfloat16_as_ushort(__float2bfloat16(ry)) << 16);
}

#define MMA4(C, A0, A1, A2, A3, B0, B1) \
    asm volatile("mma.sync.aligned.m16n8k16.row.col.f32.bf16.bf16.f32 " \
        "{%0,%1,%2,%3}, {%4,%5,%6,%7}, {%8,%9}, {%0,%1,%2,%3};" \
        : "+f"((C)[0]), "+f"((C)[1]), "+f"((C)[2]), "+f"((C)[3]) \
        : "r"(A0), "r"(A1), "r"(A2), "r"(A3), "r"(B0), "r"(B1))

// ---------------- mask dtype detection (deterministic, data-driven) -------
__global__ void classify_mask(const unsigned char* __restrict__ m, int nbytes) {
    __shared__ int f3Fmod1, f3Fany, fNzOff;
    int tid = threadIdx.x;
    if (tid == 0) { f3Fmod1 = 0; f3Fany = 0; fNzOff = 0; }
    __syncthreads();
    int l0 = 0, l1 = 0, l2 = 0;
    for (int i = tid; i < nbytes; i += blockDim.x) {
        unsigned char v = m[i];
        if (v) {
            if (v == 0x3F) { l1 = 1; if ((i & 3) == 1) l0 = 1; }
            if ((i & 3) != 0) l2 = 1;
        }
    }
    if (l0) atomicOr(&f3Fmod1, 1);
    if (l1) atomicOr(&f3Fany, 1);
    if (l2) atomicOr(&fNzOff, 1);
    __syncthreads();
    if (tid == 0) {
        int t;
        if (f3Fmod1)      t = 3;
        else if (f3Fany)  t = 2;
        else if (fNzOff)  t = 0;
        else              t = 1;
        g_maskType = t;
    }
}

__global__ void convert_mask(const void* __restrict__ m, int n) {
    int i = blockIdx.x * blockDim.x + threadIdx.x;
    if (i >= n) return;
    int t = g_maskType;
    bool masked;
    if (t == 0)      masked = ((const unsigned char*)m)[i]  != 0;
    else if (t == 1) masked = ((const int*)m)[i]            != 0;
    else if (t == 2) masked = ((const float*)m)[i]          != 0.0f;
    else             masked = ((const unsigned short*)m)[i] != 0;
    g_keep[i] = masked ? 0.0f : 1.0f;
}

// ---------------- kernel A: q encoder MLP -> scaled, split-bf16 Q ----------
__global__ void __launch_bounds__(128) encoder_kernel(
    const float* __restrict__ jq,
    const float* __restrict__ W1, const float* __restrict__ b1,
    const float* __restrict__ W2, const float* __restrict__ b2) {
    __shared__ float xs[QD];
    __shared__ float hs[64];
    int bid = blockIdx.x;            // b*32 + j
    int b = bid >> 5, j = bid & 31;
    int tid = threadIdx.x;
    for (int i = tid; i < QD; i += 128) xs[i] = jq[(size_t)bid * QD + i];
    __syncthreads();
    if (tid < 64) {
        float s = b1[tid];
        for (int r = 0; r < QD; r++) s += xs[r] * W1[r * 64 + tid];
        hs[tid] = fmaxf(s, 0.0f);
    }
    __syncthreads();
    int k0 = tid * 4;
    float s[4];
    s[0] = b2[k0]; s[1] = b2[k0 + 1]; s[2] = b2[k0 + 2]; s[3] = b2[k0 + 3];
    for (int r = 0; r < 64; r++) {
        float hv = hs[r];
        float4 w = *(const float4*)(W2 + r * 512 + k0);
        s[0] += hv * w.x; s[1] += hv * w.y; s[2] += hv * w.z; s[3] += hv * w.w;
    }
#pragma unroll
    for (int u = 0; u < 4; u++) {
        int k = k0 + u;
        int head = k >> 7, d = k & 127;
        int qi = j * 4 + head;
        float q = s[u] * QSCALE;
        __nv_bfloat16 h = __float2bfloat16(q);
        g_Qh[((size_t)b * QROWS + qi) * KD + d] = h;
        g_Ql[((size_t)b * QROWS + qi) * KD + d] =
            __float2bfloat16(q - __bfloat162float(h));
    }
}

// ---------------- kernel B1: P = exp2(Q K^T) * keep  (tensor cores) --------
// grid (64 ntiles, 64 b), 256 threads (8 warps). Tile: 128q x 64n, K=128.
// smem: Qh/Ql [128][136 halfs], Kh/Kl [64][136 halfs], keep[64].
__global__ void __launch_bounds__(256) qk_mma_kernel(const float* __restrict__ Kg) {
    extern __shared__ unsigned char smraw[];
    unsigned* Qh32 = (unsigned*)(smraw);            // 128 x 68 u32
    unsigned* Ql32 = (unsigned*)(smraw + 34816);
    unsigned* Kh32 = (unsigned*)(smraw + 69632);    // 64 x 68 u32
    unsigned* Kl32 = (unsigned*)(smraw + 87040);
    float*    keep_s = (float*)(smraw + 104448);

    int b = blockIdx.y;
    int n0 = blockIdx.x * 64;
    int tid = threadIdx.x;

    { // copy Q hi/lo tiles (each 128 rows x 64 u32), padded stride 68 u32
        const unsigned* srcH = (const unsigned*)g_Qh + (size_t)b * (QROWS * KD / 2);
        const unsigned* srcL = (const unsigned*)g_Ql + (size_t)b * (QROWS * KD / 2);
#pragma unroll
        for (int i = 0; i < 32; i++) {
            int idx = tid + i * 256;
            int r = idx >> 6, c = idx & 63;
            Qh32[r * 68 + c] = srcH[idx];
            Ql32[r * 68 + c] = srcL[idx];
        }
    }
    { // K tile: 64n x 128d f32 -> split bf16, [n][d] stride 136 halfs
#pragma unroll
        for (int i = 0; i < 8; i++) {
            int idx = tid + i * 256;            // 0..2047
            int n = idx >> 5;
            int d4 = (idx & 31) * 4;
            float4 v = *(const float4*)(Kg + ((size_t)b * NV + n0 + n) * KD + d4);
            unsigned h0, l0, h1, l1;
            splitpack(v.x, v.y, h0, l0);
            splitpack(v.z, v.w, h1, l1);
            int o = n * 68 + (d4 >> 1);
            Kh32[o] = h0; Kh32[o + 1] = h1;
            Kl32[o] = l0; Kl32[o + 1] = l1;
        }
    }
    if (tid < 64) keep_s[tid] = g_keep[b * NV + n0 + tid];
    __syncthreads();

    int w = tid >> 5, l = tid & 31, g = l >> 2, t = l & 3;
    int m0 = w * 16;
    float acc[8][4];
#pragma unroll
    for (int i = 0; i < 8; i++) { acc[i][0] = acc[i][1] = acc[i][2] = acc[i][3] = 0.0f; }

    int aBase = (m0 + g) * 68 + t;
    int bBase = g * 68 + t;
#pragma unroll
    for (int ks = 0; ks < 8; ks++) {
        int ao = aBase + ks * 8;
        unsigned ah0 = Qh32[ao], ah1 = Qh32[ao + 544], ah2 = Qh32[ao + 4], ah3 = Qh32[ao + 548];
        unsigned al0 = Ql32[ao], al1 = Ql32[ao + 544], al2 = Ql32[ao + 4], al3 = Ql32[ao + 548];
#pragma unroll
        for (int nt = 0; nt < 8; nt++) {
            int bo = bBase + nt * 544 + ks * 8;
            unsigned bh0 = Kh32[bo], bh1 = Kh32[bo + 4];
            unsigned bl0 = Kl32[bo], bl1 = Kl32[bo + 4];
            MMA4(acc[nt], ah0, ah1, ah2, ah3, bh0, bh1);
            MMA4(acc[nt], al0, al1, al2, al3, bh0, bh1);
            MMA4(acc[nt], ah0, ah1, ah2, ah3, bl0, bl1);
        }
    }

    // epilogue: p = exp2(s)*keep, split to bf16 hi/lo, packed u32 stores
    size_t row0 = ((size_t)b * QROWS + m0 + g) * (NV / 2) + (n0 >> 1);
    size_t row1 = row0 + 8 * (NV / 2);
#pragma unroll
    for (int nt = 0; nt < 8; nt++) {
        int c0 = nt * 8 + 2 * t;
        float k0f = keep_s[c0], k1f = keep_s[c0 + 1];
        float p00 = exp2f(acc[nt][0]) * k0f;
        float p01 = exp2f(acc[nt][1]) * k1f;
        float p10 = exp2f(acc[nt][2]) * k0f;
        float p11 = exp2f(acc[nt][3]) * k1f;
        unsigned h, lo;
        splitpack(p00, p01, h, lo);
        g_Ph32[row0 + nt * 4 + t] = h;
        g_Pl32[row0 + nt * 4 + t] = lo;
        splitpack(p10, p11, h, lo);
        g_Ph32[row1 + nt * 4 + t] = h;
        g_Pl32[row1 + nt * 4 + t] = lo;
    }
}

// ---------------- kernel B2: obuf[split] = P @ [V | 1]  (tensor cores) -----
// grid (4 splits, 64 b), 256 threads. Per block: 128q x 136v, K = 1024 n.
// smem: Ps hi/lo [128][72 halfs], Vs hi/lo [136][72 halfs] (V transposed).
__global__ void __launch_bounds__(256, 2) pv_mma_kernel(const float* __restrict__ Vg) {
    extern __shared__ unsigned char smraw[];
    unsigned* Psh = (unsigned*)(smraw);             // 128 x 36 u32
    unsigned* Psl = (unsigned*)(smraw + 18432);
    unsigned* Vsh = (unsigned*)(smraw + 36864);     // 136 x 36 u32
    unsigned* Vsl = (unsigned*)(smraw + 56448);
    __nv_bfloat16* VshH = (__nv_bfloat16*)Vsh;
    __nv_bfloat16* VslH = (__nv_bfloat16*)Vsl;

    int split = blockIdx.x, b = blockIdx.y;
    int tid = threadIdx.x;
    int w = tid >> 5, l = tid & 31, g = l >> 2, t = l & 3;
    int m0 = w * 16;

    float acc[17][4];
#pragma unroll
    for (int i = 0; i < 17; i++) { acc[i][0] = acc[i][1] = acc[i][2] = acc[i][3] = 0.0f; }

    for (int nc = 0; nc < 16; nc++) {
        int n0 = split * (NV / NSPLIT) + nc * 64;
        __syncthreads();
        // Ps: 128 q x 32 u32, padded stride 36 u32
#pragma unroll
        for (int i = 0; i < 16; i++) {
            int idx = tid + i * 256;
            int q = idx >> 5, c = idx & 31;
            size_t src = ((size_t)b * QROWS + q) * (NV / 2) + (n0 >> 1) + c;
            Psh[q * 36 + c] = g_Ph32[src];
            Psl[q * 36 + c] = g_Pl32[src];
        }
        // Vs: transpose 64n x 136v (ones col at v=130), split bf16
#pragma unroll
        for (int i = 0; i < 34; i++) {
            int idx = tid + i * 256;            // 0..8703
            int n = idx / 136, v = idx - n * 136;
            float val;
            if (v < VD)       val = Vg[((size_t)b * NV + n0 + n) * VD + v];
            else              val = (v == VD) ? 1.0f : 0.0f;
            __nv_bfloat16 h = __float2bfloat16(val);
            VshH[v * 72 + n] = h;
            VslH[v * 72 + n] = __float2bfloat16(val - __bfloat162float(h));
        }
        __syncthreads();

        int aBase = (m0 + g) * 36 + t;
        int bBase = g * 36 + t;
#pragma unroll
        for (int ks = 0; ks < 4; ks++) {
            int ao = aBase + ks * 8;
            unsigned ah0 = Psh[ao], ah1 = Psh[ao + 288], ah2 = Psh[ao + 4], ah3 = Psh[ao + 292];
            unsigned al0 = Psl[ao], al1 = Psl[ao + 288], al2 = Psl[ao + 4], al3 = Psl[ao + 292];
#pragma unroll
            for (int vt = 0; vt < 17; vt++) {
                int bo = bBase + vt * 288 + ks * 8;
                unsigned bh0 = Vsh[bo], bh1 = Vsh[bo + 4];
                unsigned bl0 = Vsl[bo], bl1 = Vsl[bo + 4];
                MMA4(acc[vt], ah0, ah1, ah2, ah3, bh0, bh1);
                MMA4(acc[vt], al0, al1, al2, al3, bh0, bh1);
                MMA4(acc[vt], ah0, ah1, ah2, ah3, bl0, bl1);
            }
        }
    }

    float* orow0 = g_obuf2 + (((size_t)split * BB + b) * QROWS + m0 + g) * OST;
    float* orow1 = orow0 + 8 * OST;
#pragma unroll
    for (int vt = 0; vt < 17; vt++) {
        int v0 = vt * 8 + 2 * t;
        *(float2*)(orow0 + v0) = make_float2(acc[vt][0], acc[vt][1]);
        *(float2*)(orow1 + v0) = make_float2(acc[vt][2], acc[vt][3]);
    }
}

// ---------------- kernel C: normalize + output MLP -------------------------
__global__ void __launch_bounds__(64) mlp_kernel(
    const float* __restrict__ W3, const float* __restrict__ b3,
    const float* __restrict__ W4, const float* __restrict__ b4,
    const float* __restrict__ W5, const float* __restrict__ b5,
    float* __restrict__ out) {
    __shared__ float os[520];
    __shared__ float h1[64];
    __shared__ float h2[32];
    int bid = blockIdx.x;            // b*32 + j
    int b = bid >> 5, j = bid & 31;
    int tid = threadIdx.x;           // 64
    const size_t slot = (size_t)BB * QROWS * OST;
    for (int idx = tid; idx < 520; idx += 64) {
        int h = idx / 130, v = idx - h * 130;
        size_t base = ((size_t)b * QROWS + j * 4 + h) * OST;
        float num = 0.0f, den = 0.0f;
#pragma unroll
        for (int s = 0; s < NSPLIT; s++) {
            const float* r = g_obuf2 + s * slot + base;
            num += r[v];
            den += r[130];
        }
        os[idx] = num / den;
    }
    __syncthreads();
    {
        float s = b3[tid];
        for (int r = 0; r < 520; r++) s += os[r] * W3[r * 64 + tid];
        h1[tid] = fmaxf(s, 0.0f);
    }
    __syncthreads();
    if (tid < 32) {
        float s = b4[tid];
#pragma unroll
        for (int r = 0; r < 64; r++) s += h1[r] * W4[r * 32 + tid];
        h2[tid] = fmaxf(s, 0.0f);
    }
    __syncthreads();
    if (tid < 32) {
        float v = h2[tid] * W5[tid];
#pragma unroll
        for (int off = 16; off; off >>= 1) v += __shfl_down_sync(0xffffffffu, v, off);
        if (tid == 0) out[bid] = v + b5[0];
    }
}

// ---------------- launch ----------------------------------------------------
extern "C" void kernel_launch(void* const* d_in, const int* in_sizes, int n_in,
                              void* d_out, int out_size) {
    const float* jq = (const float*)d_in[0];
    const float* Kg = (const float*)d_in[1];
    const float* Vg = (const float*)d_in[2];
    const void*  mk = d_in[3];
    const float* W1 = (const float*)d_in[4];
    const float* b1 = (const float*)d_in[5];
    const float* W2 = (const float*)d_in[6];
    const float* b2 = (const float*)d_in[7];
    const float* W3 = (const float*)d_in[8];
    const float* b3 = (const float*)d_in[9];
    const float* W4 = (const float*)d_in[10];
    const float* b4 = (const float*)d_in[11];
    const float* W5 = (const float*)d_in[12];
    const float* b5 = (const float*)d_in[13];
    float* out = (float*)d_out;

    classify_mask<<<1, 256>>>((const unsigned char*)mk, BB * NV);
    convert_mask<<<(BB * NV + 255) / 256, 256>>>(mk, BB * NV);
    encoder_kernel<<<BB * JJ, 128>>>(jq, W1, b1, W2, b2);

    static int inited = 0;
    int smem_qk = 104704;
    int smem_pv = 76032;
    cudaFuncSetAttribute(qk_mma_kernel, cudaFuncAttributeMaxDynamicSharedMemorySize, smem_qk);
    cudaFuncSetAttribute(pv_mma_kernel, cudaFuncAttributeMaxDynamicSharedMemorySize, smem_pv);
    (void)inited;

    dim3 g1(NV / 64, BB);
    qk_mma_kernel<<<g1, 256, smem_qk>>>(Kg);

    dim3 g2(NSPLIT, BB);
    pv_mma_kernel<<<g2, 256, smem_pv>>>(Vg);

    mlp_kernel<<<BB * JJ, 64>>>(W3, b3, W4, b4, W5, b5, out);
}

// round 7
// speedup vs baseline: 1.3927x; 1.1367x over previous
#include <cuda_runtime.h>
#include <cuda_bf16.h>
#include <math.h>

#define BB 64
#define JJ 32
#define NV 4096
#define QD 130
#define KD 128
#define VD 130
#define HH 4
#define QROWS 128              // J*H rows of q per batch
#define OST 136                // obuf row stride (130 vals + denom @130 + pad)
#define NSPLIT 16              // n-splits -> obuf slots
#define CHUNK 64
#define NCHUNKS ((NV / NSPLIT) / CHUNK)   // 4
// fold log2(e)/sqrt(128) into q so p = exp2f(score)
#define QSCALE (1.4426950408889634f / 11.313708498984761f)

// ---------------- device scratch (static: no runtime allocation) ----------
__device__ __nv_bfloat16 g_Qh[BB * QROWS * KD];    // [b][q][d] hi
__device__ __nv_bfloat16 g_Ql[BB * QROWS * KD];    // [b][q][d] lo
__device__ float g_obuf2[(size_t)NSPLIT * BB * QROWS * OST];
__device__ float g_keep[BB * NV];                  // 1.0 keep / 0.0 masked
__device__ int   g_maskType;

// bf16 split-pack: two floats -> (hi pair, lo pair) packed u32
__device__ __forceinline__ void splitpack(float x, float y, unsigned& hi, unsigned& lo) {
    __nv_bfloat16 hx = __float2bfloat16(x);
    __nv_bfloat16 hy = __float2bfloat16(y);
    float rx = x - __bfloat162float(hx);
    float ry = y - __bfloat162float(hy);
    hi = (unsigned)__bfloat16_as_ushort(hx) | ((unsigned)__bfloat16_as_ushort(hy) << 16);
    lo = (unsigned)__bfloat16_as_ushort(__float2bfloat16(rx))
       | ((unsigned)__bfloat16_as_ushort(__float2bfloat16(ry)) << 16);
}

#define MMA4(C, A0, A1, A2, A3, B0, B1) \
    asm volatile("mma.sync.aligned.m16n8k16.row.col.f32.bf16.bf16.f32 " \
        "{%0,%1,%2,%3}, {%4,%5,%6,%7}, {%8,%9}, {%0,%1,%2,%3};" \
        : "+f"((C)[0]), "+f"((C)[1]), "+f"((C)[2]), "+f"((C)[3]) \
        : "r"(A0), "r"(A1), "r"(A2), "r"(A3), "r"(B0), "r"(B1))

// ---------------- mask dtype detection (deterministic, data-driven) -------
__global__ void classify_mask(const unsigned char* __restrict__ m, int nbytes) {
    __shared__ int f3Fmod1, f3Fany, fNzOff;
    int tid = threadIdx.x;
    if (tid == 0) { f3Fmod1 = 0; f3Fany = 0; fNzOff = 0; }
    __syncthreads();
    int l0 = 0, l1 = 0, l2 = 0;
    for (int i = tid; i < nbytes; i += blockDim.x) {
        unsigned char v = m[i];
        if (v) {
            if (v == 0x3F) { l1 = 1; if ((i & 3) == 1) l0 = 1; }
            if ((i & 3) != 0) l2 = 1;
        }
    }
    if (l0) atomicOr(&f3Fmod1, 1);
    if (l1) atomicOr(&f3Fany, 1);
    if (l2) atomicOr(&fNzOff, 1);
    __syncthreads();
    if (tid == 0) {
        int t;
        if (f3Fmod1)      t = 3;
        else if (f3Fany)  t = 2;
        else if (fNzOff)  t = 0;
        else              t = 1;
        g_maskType = t;
    }
}

__global__ void convert_mask(const void* __restrict__ m, int n) {
    int i = blockIdx.x * blockDim.x + threadIdx.x;
    if (i >= n) return;
    int t = g_maskType;
    bool masked;
    if (t == 0)      masked = ((const unsigned char*)m)[i]  != 0;
    else if (t == 1) masked = ((const int*)m)[i]            != 0;
    else if (t == 2) masked = ((const float*)m)[i]          != 0.0f;
    else             masked = ((const unsigned short*)m)[i] != 0;
    g_keep[i] = masked ? 0.0f : 1.0f;
}

// ---------------- kernel A: q encoder MLP -> scaled, split-bf16 Q ----------
__global__ void __launch_bounds__(128) encoder_kernel(
    const float* __restrict__ jq,
    const float* __restrict__ W1, const float* __restrict__ b1,
    const float* __restrict__ W2, const float* __restrict__ b2) {
    __shared__ float xs[QD];
    __shared__ float hs[64];
    int bid = blockIdx.x;            // b*32 + j
    int b = bid >> 5, j = bid & 31;
    int tid = threadIdx.x;
    for (int i = tid; i < QD; i += 128) xs[i] = jq[(size_t)bid * QD + i];
    __syncthreads();
    if (tid < 64) {
        float s = b1[tid];
        for (int r = 0; r < QD; r++) s += xs[r] * W1[r * 64 + tid];
        hs[tid] = fmaxf(s, 0.0f);
    }
    __syncthreads();
    int k0 = tid * 4;
    float s[4];
    s[0] = b2[k0]; s[1] = b2[k0 + 1]; s[2] = b2[k0 + 2]; s[3] = b2[k0 + 3];
    for (int r = 0; r < 64; r++) {
        float hv = hs[r];
        float4 w = *(const float4*)(W2 + r * 512 + k0);
        s[0] += hv * w.x; s[1] += hv * w.y; s[2] += hv * w.z; s[3] += hv * w.w;
    }
#pragma unroll
    for (int u = 0; u < 4; u++) {
        int k = k0 + u;
        int head = k >> 7, d = k & 127;
        int qi = j * 4 + head;
        float q = s[u] * QSCALE;
        __nv_bfloat16 h = __float2bfloat16(q);
        g_Qh[((size_t)b * QROWS + qi) * KD + d] = h;
        g_Ql[((size_t)b * QROWS + qi) * KD + d] =
            __float2bfloat16(q - __bfloat162float(h));
    }
}

// ---------------- fused attention kernel ------------------------------------
// grid (NSPLIT, BB), 256 threads (8 warps). Per block: 128 q x 256 n in
// 4 chunks of 64 n. P never leaves registers.
// smem layout (bytes):
//   Qh32 @0       128 x 68 u32   (34816)
//   Ql32 @34816   128 x 68 u32
//   Kh32 @69632    64 x 68 u32   (17408)
//   Kl32 @87040
//   Vh32 @104448  136 x 36 u32   (19584)   [v][n] transposed
//   Vl32 @124032
//   keep @143616   64 f32
#define SM_TOTAL 143872
__global__ void __launch_bounds__(256) fused_attn_kernel(
    const float* __restrict__ Kg, const float* __restrict__ Vg) {
    extern __shared__ unsigned char smraw[];
    unsigned* Qh32 = (unsigned*)(smraw);
    unsigned* Ql32 = (unsigned*)(smraw + 34816);
    unsigned* Kh32 = (unsigned*)(smraw + 69632);
    unsigned* Kl32 = (unsigned*)(smraw + 87040);
    unsigned* Vh32 = (unsigned*)(smraw + 104448);
    unsigned* Vl32 = (unsigned*)(smraw + 124032);
    float* keep_s  = (float*)(smraw + 143616);
    __nv_bfloat16* VshH = (__nv_bfloat16*)Vh32;
    __nv_bfloat16* VslH = (__nv_bfloat16*)Vl32;

    int split = blockIdx.x, b = blockIdx.y;
    int tid = threadIdx.x;
    int w = tid >> 5, l = tid & 31, g = l >> 2, t = l & 3;
    int m0 = w * 16;

    // load Q hi/lo (128 rows x 64 u32 each), padded stride 68 u32
    {
        const unsigned* srcH = (const unsigned*)g_Qh + (size_t)b * (QROWS * KD / 2);
        const unsigned* srcL = (const unsigned*)g_Ql + (size_t)b * (QROWS * KD / 2);
#pragma unroll
        for (int i = 0; i < 32; i++) {
            int idx = tid + i * 256;
            int r = idx >> 6, c = idx & 63;
            Qh32[r * 68 + c] = srcH[idx];
            Ql32[r * 68 + c] = srcL[idx];
        }
    }

    float accO[17][4];
#pragma unroll
    for (int i = 0; i < 17; i++) { accO[i][0] = accO[i][1] = accO[i][2] = accO[i][3] = 0.0f; }

    for (int c = 0; c < NCHUNKS; c++) {
        int n0 = split * (NV / NSPLIT) + c * CHUNK;
        __syncthreads();   // prior chunk's MMA reads done (also orders Q writes, iter 0)

        // K chunk: 64 n x 128 d f32 -> split bf16 [n][d], stride 68 u32
#pragma unroll
        for (int i = 0; i < 8; i++) {
            int idx = tid + i * 256;            // 0..2047
            int n = idx >> 5;
            int d4 = (idx & 31) * 4;
            float4 v = *(const float4*)(Kg + ((size_t)b * NV + n0 + n) * KD + d4);
            unsigned h0, l0v, h1, l1v;
            splitpack(v.x, v.y, h0, l0v);
            splitpack(v.z, v.w, h1, l1v);
            int o = n * 68 + (d4 >> 1);
            Kh32[o] = h0; Kh32[o + 1] = h1;
            Kl32[o] = l0v; Kl32[o + 1] = l1v;
        }
        // V chunk: transpose 64 n x 136 v (ones col @130), split bf16 [v][n]
#pragma unroll
        for (int i = 0; i < 34; i++) {
            int idx = tid + i * 256;            // 0..8703
            int n = idx / 136, v = idx - n * 136;
            float val;
            if (v < VD)       val = Vg[((size_t)b * NV + n0 + n) * VD + v];
            else              val = (v == VD) ? 1.0f : 0.0f;
            __nv_bfloat16 h = __float2bfloat16(val);
            VshH[v * 72 + n] = h;
            VslH[v * 72 + n] = __float2bfloat16(val - __bfloat162float(h));
        }
        if (tid < 64) keep_s[tid] = g_keep[b * NV + n0 + tid];
        __syncthreads();

        // ---- QK: S = Q K^T (3-pass split bf16), warp tile 16q x 64n ----
        float accS[8][4];
#pragma unroll
        for (int i = 0; i < 8; i++) { accS[i][0] = accS[i][1] = accS[i][2] = accS[i][3] = 0.0f; }

        int aBase = (m0 + g) * 68 + t;
        int bBase = g * 68 + t;
#pragma unroll
        for (int ks = 0; ks < 8; ks++) {
            int ao = aBase + ks * 8;
            unsigned ah0 = Qh32[ao], ah1 = Qh32[ao + 544], ah2 = Qh32[ao + 4], ah3 = Qh32[ao + 548];
            unsigned al0 = Ql32[ao], al1 = Ql32[ao + 544], al2 = Ql32[ao + 4], al3 = Ql32[ao + 548];
#pragma unroll
            for (int nt = 0; nt < 8; nt++) {
                int bo = bBase + nt * 544 + ks * 8;
                unsigned bh0 = Kh32[bo], bh1 = Kh32[bo + 4];
                unsigned bl0 = Kl32[bo], bl1 = Kl32[bo + 4];
                MMA4(accS[nt], ah0, ah1, ah2, ah3, bh0, bh1);
                MMA4(accS[nt], al0, al1, al2, al3, bh0, bh1);
                MMA4(accS[nt], ah0, ah1, ah2, ah3, bl0, bl1);
            }
        }

        // ---- epilogue in registers: P = exp2(S)*keep, re-split to bf16 ----
        // C-frag of m16n8 == A-frag halves of m16k16 (row pair g / g+8)
        unsigned phA[8], phB[8], plA[8], plB[8];
#pragma unroll
        for (int nt = 0; nt < 8; nt++) {
            int c0 = nt * 8 + 2 * t;
            float k0f = keep_s[c0], k1f = keep_s[c0 + 1];
            float p0 = exp2f(accS[nt][0]) * k0f;
            float p1 = exp2f(accS[nt][1]) * k1f;
            float p2 = exp2f(accS[nt][2]) * k0f;
            float p3 = exp2f(accS[nt][3]) * k1f;
            splitpack(p0, p1, phA[nt], plA[nt]);
            splitpack(p2, p3, phB[nt], plB[nt]);
        }

        // ---- PV: O += P @ [V|1]^T-frags, warp tile 16q x 136v ----
#pragma unroll
        for (int ks = 0; ks < 4; ks++) {
            unsigned ah0 = phA[2 * ks], ah1 = phB[2 * ks];
            unsigned ah2 = phA[2 * ks + 1], ah3 = phB[2 * ks + 1];
            unsigned al0 = plA[2 * ks], al1 = plB[2 * ks];
            unsigned al2 = plA[2 * ks + 1], al3 = plB[2 * ks + 1];
            int bB2 = g * 36 + ks * 8 + t;
#pragma unroll
            for (int vt = 0; vt < 17; vt++) {
                int bo = bB2 + vt * 288;
                unsigned bh0 = Vh32[bo], bh1 = Vh32[bo + 4];
                unsigned bl0 = Vl32[bo], bl1 = Vl32[bo + 4];
                MMA4(accO[vt], ah0, ah1, ah2, ah3, bh0, bh1);
                MMA4(accO[vt], al0, al1, al2, al3, bh0, bh1);
                MMA4(accO[vt], ah0, ah1, ah2, ah3, bl0, bl1);
            }
        }
    }

    // write O tile to this split's obuf slot
    float* orow0 = g_obuf2 + (((size_t)split * BB + b) * QROWS + m0 + g) * OST;
    float* orow1 = orow0 + 8 * OST;
#pragma unroll
    for (int vt = 0; vt < 17; vt++) {
        int v0 = vt * 8 + 2 * t;
        *(float2*)(orow0 + v0) = make_float2(accO[vt][0], accO[vt][1]);
        *(float2*)(orow1 + v0) = make_float2(accO[vt][2], accO[vt][3]);
    }
}

// ---------------- kernel C: normalize + output MLP -------------------------
__global__ void __launch_bounds__(64) mlp_kernel(
    const float* __restrict__ W3, const float* __restrict__ b3,
    const float* __restrict__ W4, const float* __restrict__ b4,
    const float* __restrict__ W5, const float* __restrict__ b5,
    float* __restrict__ out) {
    __shared__ float os[520];
    __shared__ float h1[64];
    __shared__ float h2[32];
    int bid = blockIdx.x;            // b*32 + j
    int b = bid >> 5, j = bid & 31;
    int tid = threadIdx.x;           // 64
    const size_t slot = (size_t)BB * QROWS * OST;
    for (int idx = tid; idx < 520; idx += 64) {
        int h = idx / 130, v = idx - h * 130;
        size_t base = ((size_t)b * QROWS + j * 4 + h) * OST;
        float num = 0.0f, den = 0.0f;
#pragma unroll
        for (int s = 0; s < NSPLIT; s++) {
            const float* r = g_obuf2 + s * slot + base;
            num += r[v];
            den += r[130];
        }
        os[idx] = num / den;
    }
    __syncthreads();
    {
        float s = b3[tid];
        for (int r = 0; r < 520; r++) s += os[r] * W3[r * 64 + tid];
        h1[tid] = fmaxf(s, 0.0f);
    }
    __syncthreads();
    if (tid < 32) {
        float s = b4[tid];
#pragma unroll
        for (int r = 0; r < 64; r++) s += h1[r] * W4[r * 32 + tid];
        h2[tid] = fmaxf(s, 0.0f);
    }
    __syncthreads();
    if (tid < 32) {
        float v = h2[tid] * W5[tid];
#pragma unroll
        for (int off = 16; off; off >>= 1) v += __shfl_down_sync(0xffffffffu, v, off);
        if (tid == 0) out[bid] = v + b5[0];
    }
}

// ---------------- launch ----------------------------------------------------
extern "C" void kernel_launch(void* const* d_in, const int* in_sizes, int n_in,
                              void* d_out, int out_size) {
    const float* jq = (const float*)d_in[0];
    const float* Kg = (const float*)d_in[1];
    const float* Vg = (const float*)d_in[2];
    const void*  mk = d_in[3];
    const float* W1 = (const float*)d_in[4];
    const float* b1 = (const float*)d_in[5];
    const float* W2 = (const float*)d_in[6];
    const float* b2 = (const float*)d_in[7];
    const float* W3 = (const float*)d_in[8];
    const float* b3 = (const float*)d_in[9];
    const float* W4 = (const float*)d_in[10];
    const float* b4 = (const float*)d_in[11];
    const float* W5 = (const float*)d_in[12];
    const float* b5 = (const float*)d_in[13];
    float* out = (float*)d_out;

    classify_mask<<<1, 256>>>((const unsigned char*)mk, BB * NV);
    convert_mask<<<(BB * NV + 255) / 256, 256>>>(mk, BB * NV);
    encoder_kernel<<<BB * JJ, 128>>>(jq, W1, b1, W2, b2);

    cudaFuncSetAttribute(fused_attn_kernel,
                         cudaFuncAttributeMaxDynamicSharedMemorySize, SM_TOTAL);
    dim3 g1(NSPLIT, BB);
    fused_attn_kernel<<<g1, 256, SM_TOTAL>>>(Kg, Vg);

    mlp_kernel<<<BB * JJ, 64>>>(W3, b3, W4, b4, W5, b5, out);
}

// round 8
// speedup vs baseline: 3.5749x; 2.5668x over previous
#include <cuda_runtime.h>
#include <cuda_bf16.h>
#include <math.h>

#define BB 64
#define JJ 32
#define NV 4096
#define QD 130
#define KD 128
#define VD 130
#define HH 4
#define QROWS 128              // J*H rows of q per batch
#define OST 136                // obuf row stride (130 vals + denom @130 + pad)
#define NSPLIT 16              // n-splits -> obuf slots
#define CHUNK 64
#define NCHUNKS ((NV / NSPLIT) / CHUNK)   // 4
// fold log2(e)/sqrt(128) into q so p = exp2f(score)
#define QSCALE (1.4426950408889634f / 11.313708498984761f)

// ---------------- device scratch (static: no runtime allocation) ----------
__device__ __nv_bfloat16 g_Qh[BB * QROWS * KD];    // [b][q][d] hi
__device__ __nv_bfloat16 g_Ql[BB * QROWS * KD];    // [b][q][d] lo
__device__ float g_obuf2[(size_t)NSPLIT * BB * QROWS * OST];
__device__ float g_keep[BB * NV];                  // 1.0 keep / 0.0 masked
__device__ int   g_flags[3];                       // mask-dtype evidence flags

// bf16 split-pack: two floats -> (hi pair, lo pair) packed u32
__device__ __forceinline__ void splitpack(float x, float y, unsigned& hi, unsigned& lo) {
    __nv_bfloat16 hx = __float2bfloat16(x);
    __nv_bfloat16 hy = __float2bfloat16(y);
    float rx = x - __bfloat162float(hx);
    float ry = y - __bfloat162float(hy);
    hi = (unsigned)__bfloat16_as_ushort(hx) | ((unsigned)__bfloat16_as_ushort(hy) << 16);
    lo = (unsigned)__bfloat16_as_ushort(__float2bfloat16(rx))
       | ((unsigned)__bfloat16_as_ushort(__float2bfloat16(ry)) << 16);
}

#define MMA4(C, A0, A1, A2, A3, B0, B1) \
    asm volatile("mma.sync.aligned.m16n8k16.row.col.f32.bf16.bf16.f32 " \
        "{%0,%1,%2,%3}, {%4,%5,%6,%7}, {%8,%9}, {%0,%1,%2,%3};" \
        : "+f"((C)[0]), "+f"((C)[1]), "+f"((C)[2]), "+f"((C)[3]) \
        : "r"(A0), "r"(A1), "r"(A2), "r"(A3), "r"(B0), "r"(B1))

#define LDSM_X4(R0, R1, R2, R3, ADDR) \
    asm volatile("ldmatrix.sync.aligned.m8n8.x4.shared.b16 {%0,%1,%2,%3}, [%4];" \
        : "=r"(R0), "=r"(R1), "=r"(R2), "=r"(R3) : "r"(ADDR))

#define LDSM_X2(R0, R1, ADDR) \
    asm volatile("ldmatrix.sync.aligned.m8n8.x2.shared.b16 {%0,%1}, [%2];" \
        : "=r"(R0), "=r"(R1) : "r"(ADDR))

// ---------------- mask dtype detection (deterministic, data-driven) -------
__global__ void zero_flags() {
    if (threadIdx.x < 3) g_flags[threadIdx.x] = 0;
}

// 64 blocks x 256 threads, uint4 loads over the first 256 KB (safe for
// u8 exact size; f32/i32 scan the first quarter -- plenty of evidence).
__global__ void classify_mask(const uint4* __restrict__ m) {
    int gid = blockIdx.x * 256 + threadIdx.x;   // 0..16383
    uint4 v = m[gid];
    unsigned wrd[4] = {v.x, v.y, v.z, v.w};
    bool l0 = false, l1 = false, l2 = false;
#pragma unroll
    for (int wI = 0; wI < 4; wI++) {
        unsigned x = wrd[wI];
        unsigned b0 = x & 0xFF, b1 = (x >> 8) & 0xFF, b2 = (x >> 16) & 0xFF, b3 = x >> 24;
        if (b1 == 0x3F) { l0 = true; }
        if (b0 == 0x3F || b1 == 0x3F || b2 == 0x3F || b3 == 0x3F) l1 = true;
        if (b1 | b2 | b3) l2 = true;
    }
    unsigned m0 = __ballot_sync(0xFFFFFFFFu, l0);
    unsigned m1 = __ballot_sync(0xFFFFFFFFu, l1);
    unsigned m2 = __ballot_sync(0xFFFFFFFFu, l2);
    if ((threadIdx.x & 31) == 0) {
        if (m0) atomicOr(&g_flags[0], 1);
        if (m1) atomicOr(&g_flags[1], 1);
        if (m2) atomicOr(&g_flags[2], 1);
    }
}

__global__ void convert_mask(const void* __restrict__ m, int n) {
    int i = blockIdx.x * blockDim.x + threadIdx.x;
    if (i >= n) return;
    int t;
    if (g_flags[0])      t = 3;  // bf16 (0x3F at odd byte offset)
    else if (g_flags[1]) t = 2;  // f32 (0x3F only at i%4==3)
    else if (g_flags[2]) t = 0;  // raw u8 bytes
    else                 t = 1;  // i32 0/1
    bool masked;
    if (t == 0)      masked = ((const unsigned char*)m)[i]  != 0;
    else if (t == 1) masked = ((const int*)m)[i]            != 0;
    else if (t == 2) masked = ((const float*)m)[i]          != 0.0f;
    else             masked = ((const unsigned short*)m)[i] != 0;
    g_keep[i] = masked ? 0.0f : 1.0f;
}

// ---------------- kernel A: q encoder MLP -> scaled, split-bf16 Q ----------
__global__ void __launch_bounds__(128) encoder_kernel(
    const float* __restrict__ jq,
    const float* __restrict__ W1, const float* __restrict__ b1,
    const float* __restrict__ W2, const float* __restrict__ b2) {
    __shared__ float xs[QD];
    __shared__ float hs[64];
    int bid = blockIdx.x;            // b*32 + j
    int b = bid >> 5, j = bid & 31;
    int tid = threadIdx.x;
    for (int i = tid; i < QD; i += 128) xs[i] = jq[(size_t)bid * QD + i];
    __syncthreads();
    if (tid < 64) {
        float s = b1[tid];
        for (int r = 0; r < QD; r++) s += xs[r] * W1[r * 64 + tid];
        hs[tid] = fmaxf(s, 0.0f);
    }
    __syncthreads();
    int k0 = tid * 4;
    float s[4];
    s[0] = b2[k0]; s[1] = b2[k0 + 1]; s[2] = b2[k0 + 2]; s[3] = b2[k0 + 3];
    for (int r = 0; r < 64; r++) {
        float hv = hs[r];
        float4 w = *(const float4*)(W2 + r * 512 + k0);
        s[0] += hv * w.x; s[1] += hv * w.y; s[2] += hv * w.z; s[3] += hv * w.w;
    }
#pragma unroll
    for (int u = 0; u < 4; u++) {
        int k = k0 + u;
        int head = k >> 7, d = k & 127;
        int qi = j * 4 + head;
        float q = s[u] * QSCALE;
        __nv_bfloat16 h = __float2bfloat16(q);
        g_Qh[((size_t)b * QROWS + qi) * KD + d] = h;
        g_Ql[((size_t)b * QROWS + qi) * KD + d] =
            __float2bfloat16(q - __bfloat162float(h));
    }
}

// ---------------- fused attention kernel ------------------------------------
// grid (NSPLIT, BB), 256 threads (8 warps). Per block: 128 q x 256 n in
// 4 chunks of 64 n. P never leaves registers. All fragment loads via ldmatrix.
#define SM_TOTAL 143872
__global__ void __launch_bounds__(256) fused_attn_kernel(
    const float* __restrict__ Kg, const float* __restrict__ Vg) {
    extern __shared__ unsigned char smraw[];
    unsigned* Qh32 = (unsigned*)(smraw);            // 128 x 68 u32
    unsigned* Ql32 = (unsigned*)(smraw + 34816);
    unsigned* Kh32 = (unsigned*)(smraw + 69632);    // 64 x 68 u32
    unsigned* Kl32 = (unsigned*)(smraw + 87040);
    unsigned* Vh32 = (unsigned*)(smraw + 104448);   // 136 x 36 u32 [v][n]
    unsigned* Vl32 = (unsigned*)(smraw + 124032);
    float* keep_s  = (float*)(smraw + 143616);
    __nv_bfloat16* VshH = (__nv_bfloat16*)Vh32;
    __nv_bfloat16* VslH = (__nv_bfloat16*)Vl32;

    int split = blockIdx.x, b = blockIdx.y;
    int tid = threadIdx.x;
    int w = tid >> 5, l = tid & 31, g = l >> 2, t = l & 3;
    int m0 = w * 16;

    // ldmatrix lane->address mapping
    int rowA = l & 15;                       // A: 16 rows
    int colA = (l >> 4) * 4;                 // u32 col offset (k+8 halves)
    int rowB = (l & 7) + ((l >> 4) << 3);    // B: lanes 16+ -> rows+8
    int colB = ((l >> 3) & 1) * 4;

    unsigned QhU = (unsigned)__cvta_generic_to_shared(Qh32);
    unsigned QlU = (unsigned)__cvta_generic_to_shared(Ql32);
    unsigned KhU = (unsigned)__cvta_generic_to_shared(Kh32);
    unsigned KlU = (unsigned)__cvta_generic_to_shared(Kl32);
    unsigned VhU = (unsigned)__cvta_generic_to_shared(Vh32);
    unsigned VlU = (unsigned)__cvta_generic_to_shared(Vl32);

    unsigned aH  = QhU + (((m0 + rowA) * 68) + colA) * 4;
    unsigned aL  = QlU + (((m0 + rowA) * 68) + colA) * 4;
    unsigned bKh = KhU + ((rowB * 68) + colB) * 4;
    unsigned bKl = KlU + ((rowB * 68) + colB) * 4;
    unsigned bVh = VhU + ((rowB * 36) + colB) * 4;
    unsigned bVl = VlU + ((rowB * 36) + colB) * 4;
    unsigned bV2h = VhU + (((128 + (l & 7)) * 36) + colB) * 4;
    unsigned bV2l = VlU + (((128 + (l & 7)) * 36) + colB) * 4;

    // load Q hi/lo (128 rows x 64 u32 each), padded stride 68 u32
    {
        const unsigned* srcH = (const unsigned*)g_Qh + (size_t)b * (QROWS * KD / 2);
        const unsigned* srcL = (const unsigned*)g_Ql + (size_t)b * (QROWS * KD / 2);
#pragma unroll
        for (int i = 0; i < 32; i++) {
            int idx = tid + i * 256;
            int r = idx >> 6, c = idx & 63;
            Qh32[r * 68 + c] = srcH[idx];
            Ql32[r * 68 + c] = srcL[idx];
        }
    }

    float accO[17][4];
#pragma unroll
    for (int i = 0; i < 17; i++) { accO[i][0] = accO[i][1] = accO[i][2] = accO[i][3] = 0.0f; }

    for (int c = 0; c < NCHUNKS; c++) {
        int n0 = split * (NV / NSPLIT) + c * CHUNK;
        __syncthreads();   // prior chunk's MMA reads done (also orders Q writes, iter 0)

        // K chunk: 64 n x 128 d f32 -> split bf16 [n][d], stride 68 u32
#pragma unroll
        for (int i = 0; i < 8; i++) {
            int idx = tid + i * 256;            // 0..2047
            int n = idx >> 5;
            int d4 = (idx & 31) * 4;
            float4 v = *(const float4*)(Kg + ((size_t)b * NV + n0 + n) * KD + d4);
            unsigned h0, l0v, h1, l1v;
            splitpack(v.x, v.y, h0, l0v);
            splitpack(v.z, v.w, h1, l1v);
            int o = n * 68 + (d4 >> 1);
            Kh32[o] = h0; Kh32[o + 1] = h1;
            Kl32[o] = l0v; Kl32[o + 1] = l1v;
        }
        // V chunk: transpose 64 n x 136 v (ones col @130), split bf16 [v][n]
#pragma unroll
        for (int i = 0; i < 34; i++) {
            int idx = tid + i * 256;            // 0..8703
            int n = idx / 136, v = idx - n * 136;
            float val;
            if (v < VD)       val = Vg[((size_t)b * NV + n0 + n) * VD + v];
            else              val = (v == VD) ? 1.0f : 0.0f;
            __nv_bfloat16 h = __float2bfloat16(val);
            VshH[v * 72 + n] = h;
            VslH[v * 72 + n] = __float2bfloat16(val - __bfloat162float(h));
        }
        if (tid < 64) keep_s[tid] = g_keep[b * NV + n0 + tid];
        __syncthreads();

        // ---- QK: S = Q K^T (3-pass split bf16), warp tile 16q x 64n ----
        float accS[8][4];
#pragma unroll
        for (int i = 0; i < 8; i++) { accS[i][0] = accS[i][1] = accS[i][2] = accS[i][3] = 0.0f; }

#pragma unroll
        for (int ks = 0; ks < 8; ks++) {
            unsigned ah0, ah1, ah2, ah3, al0, al1, al2, al3;
            LDSM_X4(ah0, ah1, ah2, ah3, aH + ks * 32);
            LDSM_X4(al0, al1, al2, al3, aL + ks * 32);
#pragma unroll
            for (int ntp = 0; ntp < 4; ntp++) {
                unsigned h0, h1, h2, h3, q0, q1, q2, q3;
                LDSM_X4(h0, h1, h2, h3, bKh + ntp * 4352 + ks * 32);
                LDSM_X4(q0, q1, q2, q3, bKl + ntp * 4352 + ks * 32);
                MMA4(accS[2 * ntp], ah0, ah1, ah2, ah3, h0, h1);
                MMA4(accS[2 * ntp], al0, al1, al2, al3, h0, h1);
                MMA4(accS[2 * ntp], ah0, ah1, ah2, ah3, q0, q1);
                MMA4(accS[2 * ntp + 1], ah0, ah1, ah2, ah3, h2, h3);
                MMA4(accS[2 * ntp + 1], al0, al1, al2, al3, h2, h3);
                MMA4(accS[2 * ntp + 1], ah0, ah1, ah2, ah3, q2, q3);
            }
        }

        // ---- epilogue in registers: P = exp2(S)*keep, re-split to bf16 ----
        unsigned phA[8], phB[8], plA[8], plB[8];
#pragma unroll
        for (int nt = 0; nt < 8; nt++) {
            int c0 = nt * 8 + 2 * t;
            float k0f = keep_s[c0], k1f = keep_s[c0 + 1];
            float p0 = exp2f(accS[nt][0]) * k0f;
            float p1 = exp2f(accS[nt][1]) * k1f;
            float p2 = exp2f(accS[nt][2]) * k0f;
            float p3 = exp2f(accS[nt][3]) * k1f;
            splitpack(p0, p1, phA[nt], plA[nt]);
            splitpack(p2, p3, phB[nt], plB[nt]);
        }

        // ---- PV: O += P @ [V|1]^T, warp tile 16q x 136v ----
#pragma unroll
        for (int ks = 0; ks < 4; ks++) {
            unsigned ah0 = phA[2 * ks], ah1 = phB[2 * ks];
            unsigned ah2 = phA[2 * ks + 1], ah3 = phB[2 * ks + 1];
            unsigned al0 = plA[2 * ks], al1 = plB[2 * ks];
            unsigned al2 = plA[2 * ks + 1], al3 = plB[2 * ks + 1];
#pragma unroll
            for (int vtp = 0; vtp < 8; vtp++) {
                unsigned h0, h1, h2, h3, q0, q1, q2, q3;
                LDSM_X4(h0, h1, h2, h3, bVh + vtp * 2304 + ks * 32);
                LDSM_X4(q0, q1, q2, q3, bVl + vtp * 2304 + ks * 32);
                MMA4(accO[2 * vtp], ah0, ah1, ah2, ah3, h0, h1);
                MMA4(accO[2 * vtp], al0, al1, al2, al3, h0, h1);
                MMA4(accO[2 * vtp], ah0, ah1, ah2, ah3, q0, q1);
                MMA4(accO[2 * vtp + 1], ah0, ah1, ah2, ah3, h2, h3);
                MMA4(accO[2 * vtp + 1], al0, al1, al2, al3, h2, h3);
                MMA4(accO[2 * vtp + 1], ah0, ah1, ah2, ah3, q2, q3);
            }
            { // tail tile v = 128..135 (includes ones column @130)
                unsigned h0, h1, q0, q1;
                LDSM_X2(h0, h1, bV2h + ks * 32);
                LDSM_X2(q0, q1, bV2l + ks * 32);
                MMA4(accO[16], ah0, ah1, ah2, ah3, h0, h1);
                MMA4(accO[16], al0, al1, al2, al3, h0, h1);
                MMA4(accO[16], ah0, ah1, ah2, ah3, q0, q1);
            }
        }
    }

    // write O tile to this split's obuf slot
    float* orow0 = g_obuf2 + (((size_t)split * BB + b) * QROWS + m0 + g) * OST;
    float* orow1 = orow0 + 8 * OST;
#pragma unroll
    for (int vt = 0; vt < 17; vt++) {
        int v0 = vt * 8 + 2 * t;
        *(float2*)(orow0 + v0) = make_float2(accO[vt][0], accO[vt][1]);
        *(float2*)(orow1 + v0) = make_float2(accO[vt][2], accO[vt][3]);
    }
}

// ---------------- kernel C: coalesced slot-reduce + normalize + MLP --------
__global__ void __launch_bounds__(128) mlp_kernel(
    const float* __restrict__ W3, const float* __restrict__ b3,
    const float* __restrict__ W4, const float* __restrict__ b4,
    const float* __restrict__ W5, const float* __restrict__ b5,
    float* __restrict__ out) {
    __shared__ float os2[544];
    __shared__ float os[520];
    __shared__ float h1[64];
    __shared__ float h2[32];
    int bid = blockIdx.x;            // b*32 + j
    int b = bid >> 5, j = bid & 31;
    int tid = threadIdx.x;           // 128
    const size_t slot = (size_t)BB * QROWS * OST;
    // rows j*4..j*4+3 are contiguous (4*136 = 544 floats) within each slot
    size_t base = ((size_t)b * QROWS + j * 4) * OST;
#pragma unroll
    for (int r = 0; r < 5; r++) {
        int idx = tid + r * 128;
        if (idx < 544) {
            float s = 0.0f;
#pragma unroll
            for (int sp = 0; sp < NSPLIT; sp++) s += g_obuf2[sp * slot + base + idx];
            os2[idx] = s;
        }
    }
    __syncthreads();
#pragma unroll
    for (int r = 0; r < 5; r++) {
        int idx = tid + r * 128;
        if (idx < 520) {
            int h = idx / 130, v = idx - h * 130;
            os[idx] = os2[h * 136 + v] / os2[h * 136 + 130];
        }
    }
    __syncthreads();
    if (tid < 64) {
        float s = b3[tid];
        for (int r = 0; r < 520; r++) s += os[r] * W3[r * 64 + tid];
        h1[tid] = fmaxf(s, 0.0f);
    }
    __syncthreads();
    if (tid < 32) {
        float s = b4[tid];
#pragma unroll
        for (int r = 0; r < 64; r++) s += h1[r] * W4[r * 32 + tid];
        h2[tid] = fmaxf(s, 0.0f);
    }
    __syncthreads();
    if (tid < 32) {
        float v = h2[tid] * W5[tid];
#pragma unroll
        for (int off = 16; off; off >>= 1) v += __shfl_down_sync(0xffffffffu, v, off);
        if (tid == 0) out[bid] = v + b5[0];
    }
}

// ---------------- launch ----------------------------------------------------
extern "C" void kernel_launch(void* const* d_in, const int* in_sizes, int n_in,
                              void* d_out, int out_size) {
    const float* jq = (const float*)d_in[0];
    const float* Kg = (const float*)d_in[1];
    const float* Vg = (const float*)d_in[2];
    const void*  mk = d_in[3];
    const float* W1 = (const float*)d_in[4];
    const float* b1 = (const float*)d_in[5];
    const float* W2 = (const float*)d_in[6];
    const float* b2 = (const float*)d_in[7];
    const float* W3 = (const float*)d_in[8];
    const float* b3 = (const float*)d_in[9];
    const float* W4 = (const float*)d_in[10];
    const float* b4 = (const float*)d_in[11];
    const float* W5 = (const float*)d_in[12];
    const float* b5 = (const float*)d_in[13];
    float* out = (float*)d_out;

    zero_flags<<<1, 32>>>();
    classify_mask<<<64, 256>>>((const uint4*)mk);
    convert_mask<<<(BB * NV + 255) / 256, 256>>>(mk, BB * NV);
    encoder_kernel<<<BB * JJ, 128>>>(jq, W1, b1, W2, b2);

    cudaFuncSetAttribute(fused_attn_kernel,
                         cudaFuncAttributeMaxDynamicSharedMemorySize, SM_TOTAL);
    dim3 g1(NSPLIT, BB);
    fused_attn_kernel<<<g1, 256, SM_TOTAL>>>(Kg, Vg);

    mlp_kernel<<<BB * JJ, 128>>>(W3, b3, W4, b4, W5, b5, out);
}

// round 9
// speedup vs baseline: 4.4423x; 1.2426x over previous
#include <cuda_runtime.h>
#include <cuda_bf16.h>
#include <math.h>

#define BB 64
#define JJ 32
#define NV 4096
#define QD 130
#define KD 128
#define VD 130
#define HH 4
#define QROWS 128              // J*H rows of q per batch
#define OST 136                // obuf row stride (130 vals + denom @130 + pad)
#define NSPLIT 16              // n-splits -> obuf slots
#define CHUNK 64
#define NCHUNKS ((NV / NSPLIT) / CHUNK)   // 4
// fold log2(e)/sqrt(128) into q so p = exp2f(score)
#define QSCALE (1.4426950408889634f / 11.313708498984761f)

// ---------------- device scratch (static: no runtime allocation) ----------
__device__ __nv_bfloat16 g_Qh[BB * QROWS * KD];    // [b][q][d] hi
__device__ __nv_bfloat16 g_Ql[BB * QROWS * KD];    // [b][q][d] lo
__device__ float g_obuf2[(size_t)NSPLIT * BB * QROWS * OST];
__device__ float g_keep[BB * NV];                  // 1.0 keep / 0.0 masked
__device__ int   g_flags[3];                       // mask-dtype evidence flags

// split-pack via bf16x2 CVT: two floats -> (hi pair, lo pair) packed u32
__device__ __forceinline__ void splitpack2(float x, float y, unsigned& hi, unsigned& lo) {
    unsigned h;
    asm("cvt.rn.bf16x2.f32 %0, %1, %2;" : "=r"(h) : "f"(y), "f"(x));  // x->low, y->high
    float hx = __uint_as_float(h << 16);
    float hy = __uint_as_float(h & 0xFFFF0000u);
    float rx = x - hx;
    float ry = y - hy;
    unsigned l;
    asm("cvt.rn.bf16x2.f32 %0, %1, %2;" : "=r"(l) : "f"(ry), "f"(rx));
    hi = h; lo = l;
}

#define MMA4(C, A0, A1, A2, A3, B0, B1) \
    asm volatile("mma.sync.aligned.m16n8k16.row.col.f32.bf16.bf16.f32 " \
        "{%0,%1,%2,%3}, {%4,%5,%6,%7}, {%8,%9}, {%0,%1,%2,%3};" \
        : "+f"((C)[0]), "+f"((C)[1]), "+f"((C)[2]), "+f"((C)[3]) \
        : "r"(A0), "r"(A1), "r"(A2), "r"(A3), "r"(B0), "r"(B1))

#define LDSM_X4(R0, R1, R2, R3, ADDR) \
    asm volatile("ldmatrix.sync.aligned.m8n8.x4.shared.b16 {%0,%1,%2,%3}, [%4];" \
        : "=r"(R0), "=r"(R1), "=r"(R2), "=r"(R3) : "r"(ADDR))

#define LDSM_X2(R0, R1, ADDR) \
    asm volatile("ldmatrix.sync.aligned.m8n8.x2.shared.b16 {%0,%1}, [%2];" \
        : "=r"(R0), "=r"(R1) : "r"(ADDR))

__device__ __forceinline__ void cpa16(unsigned dst, const void* src) {
    asm volatile("cp.async.cg.shared.global [%0], [%1], 16;" :: "r"(dst), "l"(src));
}

// ---------------- mask dtype detection (deterministic, data-driven) -------
__global__ void zero_flags() {
    if (threadIdx.x < 3) g_flags[threadIdx.x] = 0;
}

__global__ void classify_mask(const uint4* __restrict__ m) {
    int gid = blockIdx.x * 256 + threadIdx.x;   // 0..16383
    uint4 v = m[gid];
    unsigned wrd[4] = {v.x, v.y, v.z, v.w};
    bool l0 = false, l1 = false, l2 = false;
#pragma unroll
    for (int wI = 0; wI < 4; wI++) {
        unsigned x = wrd[wI];
        unsigned b0 = x & 0xFF, b1 = (x >> 8) & 0xFF, b2 = (x >> 16) & 0xFF, b3 = x >> 24;
        if (b1 == 0x3F) { l0 = true; }
        if (b0 == 0x3F || b1 == 0x3F || b2 == 0x3F || b3 == 0x3F) l1 = true;
        if (b1 | b2 | b3) l2 = true;
    }
    unsigned m0 = __ballot_sync(0xFFFFFFFFu, l0);
    unsigned m1 = __ballot_sync(0xFFFFFFFFu, l1);
    unsigned m2 = __ballot_sync(0xFFFFFFFFu, l2);
    if ((threadIdx.x & 31) == 0) {
        if (m0) atomicOr(&g_flags[0], 1);
        if (m1) atomicOr(&g_flags[1], 1);
        if (m2) atomicOr(&g_flags[2], 1);
    }
}

__global__ void convert_mask(const void* __restrict__ m, int n) {
    int i = blockIdx.x * blockDim.x + threadIdx.x;
    if (i >= n) return;
    int t;
    if (g_flags[0])      t = 3;  // bf16 (0x3F at odd byte offset)
    else if (g_flags[1]) t = 2;  // f32 (0x3F only at i%4==3)
    else if (g_flags[2]) t = 0;  // raw u8 bytes
    else                 t = 1;  // i32 0/1
    bool masked;
    if (t == 0)      masked = ((const unsigned char*)m)[i]  != 0;
    else if (t == 1) masked = ((const int*)m)[i]            != 0;
    else if (t == 2) masked = ((const float*)m)[i]          != 0.0f;
    else             masked = ((const unsigned short*)m)[i] != 0;
    g_keep[i] = masked ? 0.0f : 1.0f;
}

// ---------------- kernel A: q encoder MLP -> scaled, split-bf16 Q ----------
__global__ void __launch_bounds__(128) encoder_kernel(
    const float* __restrict__ jq,
    const float* __restrict__ W1, const float* __restrict__ b1,
    const float* __restrict__ W2, const float* __restrict__ b2) {
    __shared__ float xs[QD];
    __shared__ float hs[64];
    int bid = blockIdx.x;            // b*32 + j
    int b = bid >> 5, j = bid & 31;
    int tid = threadIdx.x;
    for (int i = tid; i < QD; i += 128) xs[i] = jq[(size_t)bid * QD + i];
    __syncthreads();
    if (tid < 64) {
        float s = b1[tid];
        for (int r = 0; r < QD; r++) s += xs[r] * W1[r * 64 + tid];
        hs[tid] = fmaxf(s, 0.0f);
    }
    __syncthreads();
    int k0 = tid * 4;
    float s[4];
    s[0] = b2[k0]; s[1] = b2[k0 + 1]; s[2] = b2[k0 + 2]; s[3] = b2[k0 + 3];
    for (int r = 0; r < 64; r++) {
        float hv = hs[r];
        float4 w = *(const float4*)(W2 + r * 512 + k0);
        s[0] += hv * w.x; s[1] += hv * w.y; s[2] += hv * w.z; s[3] += hv * w.w;
    }
#pragma unroll
    for (int u = 0; u < 4; u++) {
        int k = k0 + u;
        int head = k >> 7, d = k & 127;
        int qi = j * 4 + head;
        float q = s[u] * QSCALE;
        __nv_bfloat16 h = __float2bfloat16(q);
        g_Qh[((size_t)b * QROWS + qi) * KD + d] = h;
        g_Ql[((size_t)b * QROWS + qi) * KD + d] =
            __float2bfloat16(q - __bfloat162float(h));
    }
}

// ---------------- fused attention kernel ------------------------------------
// grid (NSPLIT, BB), 256 threads (8 warps). Per block: 128 q x 256 n in
// 4 chunks of 64 n. P never leaves registers. cp.async staging overlaps
// gmem latency with the MMA phase of the previous chunk.
#define OFF_QH   0
#define OFF_QL   34816
#define OFF_KH   69632
#define OFF_KL   87040
#define OFF_VH   104448
#define OFF_VL   124032
#define OFF_KSTA 143616     // f32[8192]  raw K chunk
#define OFF_VSTA 176384     // f32[8320]  raw V chunk
#define OFF_KEEP 209664     // f32[256]   keep for all 4 chunks
#define SM_TOTAL 210688
__global__ void __launch_bounds__(256) fused_attn_kernel(
    const float* __restrict__ Kg, const float* __restrict__ Vg) {
    extern __shared__ unsigned char smraw[];
    unsigned* Qh32 = (unsigned*)(smraw + OFF_QH);   // 128 x 68 u32
    unsigned* Ql32 = (unsigned*)(smraw + OFF_QL);
    unsigned* Kh32 = (unsigned*)(smraw + OFF_KH);   // 64 x 68 u32
    unsigned* Kl32 = (unsigned*)(smraw + OFF_KL);
    unsigned* Vh32 = (unsigned*)(smraw + OFF_VH);   // 136 x 36 u32 [v][n]
    unsigned* Vl32 = (unsigned*)(smraw + OFF_VL);
    float* Ksta    = (float*)(smraw + OFF_KSTA);
    float* Vsta    = (float*)(smraw + OFF_VSTA);
    float* keepAll = (float*)(smraw + OFF_KEEP);

    int split = blockIdx.x, b = blockIdx.y;
    int tid = threadIdx.x;
    int w = tid >> 5, l = tid & 31, g = l >> 2, t = l & 3;
    int m0 = w * 16;
    int nblk = split * (NV / NSPLIT);

    // ldmatrix lane->address mapping
    int rowA = l & 15;
    int colA = (l >> 4) * 4;
    int rowB = (l & 7) + ((l >> 4) << 3);
    int colB = ((l >> 3) & 1) * 4;

    unsigned QhU = (unsigned)__cvta_generic_to_shared(Qh32);
    unsigned QlU = (unsigned)__cvta_generic_to_shared(Ql32);
    unsigned KhU = (unsigned)__cvta_generic_to_shared(Kh32);
    unsigned KlU = (unsigned)__cvta_generic_to_shared(Kl32);
    unsigned VhU = (unsigned)__cvta_generic_to_shared(Vh32);
    unsigned VlU = (unsigned)__cvta_generic_to_shared(Vl32);
    unsigned KstaU = (unsigned)__cvta_generic_to_shared(Ksta);
    unsigned VstaU = (unsigned)__cvta_generic_to_shared(Vsta);
    unsigned keepU = (unsigned)__cvta_generic_to_shared(keepAll);

    unsigned aH  = QhU + (((m0 + rowA) * 68) + colA) * 4;
    unsigned aL  = QlU + (((m0 + rowA) * 68) + colA) * 4;
    unsigned bKh = KhU + ((rowB * 68) + colB) * 4;
    unsigned bKl = KlU + ((rowB * 68) + colB) * 4;
    unsigned bVh = VhU + ((rowB * 36) + colB) * 4;
    unsigned bVl = VlU + ((rowB * 36) + colB) * 4;
    unsigned bV2h = VhU + (((128 + (l & 7)) * 36) + colB) * 4;
    unsigned bV2l = VlU + (((128 + (l & 7)) * 36) + colB) * 4;

    // ---- prologue: issue all initial cp.async traffic in one group ----
    {
        const char* srcH = (const char*)((const unsigned*)g_Qh + (size_t)b * (QROWS * KD / 2));
        const char* srcL = (const char*)((const unsigned*)g_Ql + (size_t)b * (QROWS * KD / 2));
#pragma unroll
        for (int i = 0; i < 8; i++) {
            int idx = tid + i * 256;
            int r = idx >> 4, c16 = idx & 15;
            unsigned dofs = (unsigned)(r * 272 + c16 * 16);
            cpa16(QhU + dofs, srcH + idx * 16);
            cpa16(QlU + dofs, srcL + idx * 16);
        }
        if (tid < 64)
            cpa16(keepU + tid * 16,
                  (const char*)(g_keep + (size_t)b * NV + nblk) + tid * 16);
        // chunk 0 raw K/V
        const char* ksrc = (const char*)(Kg + ((size_t)b * NV + nblk) * KD);
        const char* vsrc = (const char*)(Vg + ((size_t)b * NV + nblk) * VD);
#pragma unroll
        for (int i = 0; i < 8; i++) {
            int off = (tid + i * 256) * 16;
            cpa16(KstaU + off, ksrc + off);
        }
#pragma unroll
        for (int i = 0; i < 9; i++) {
            int idx = tid + i * 256;
            if (idx < 2080) cpa16(VstaU + idx * 16, vsrc + idx * 16);
        }
        asm volatile("cp.async.commit_group;" ::: "memory");
    }
    // ones/zero rows of V bufs (v = 130..135), written once
    for (int i = tid; i < 192; i += 256) {
        int v = 130 + (i >> 5), np = i & 31;
        Vh32[v * 36 + np] = (v == 130) ? 0x3F803F80u : 0u;
        Vl32[v * 36 + np] = 0u;
    }

    float accO[17][4];
#pragma unroll
    for (int i = 0; i < 17; i++) { accO[i][0] = accO[i][1] = accO[i][2] = accO[i][3] = 0.0f; }

    for (int c = 0; c < NCHUNKS; c++) {
        asm volatile("cp.async.wait_group 0;" ::: "memory");
        __syncthreads();   // staging ready; prior chunk's MMA reads done

        // ---- convert staging -> split-bf16 K/V buffers ----
#pragma unroll
        for (int i = 0; i < 8; i++) {
            int idx = tid + i * 256;            // 0..2047
            int n = idx >> 5;
            int d4 = (idx & 31) * 4;
            float4 v = *(const float4*)(Ksta + n * 128 + d4);
            unsigned h0, l0v, h1, l1v;
            splitpack2(v.x, v.y, h0, l0v);
            splitpack2(v.z, v.w, h1, l1v);
            int o = n * 68 + (d4 >> 1);
            Kh32[o] = h0; Kh32[o + 1] = h1;
            Kl32[o] = l0v; Kl32[o + 1] = l1v;
        }
#pragma unroll
        for (int i = 0; i < 17; i++) {
            int p = tid + i * 256;              // pair index over 130 v x 32 npairs
            if (p < 4160) {
                int np = p / 130;
                int v = p - np * 130;
                float x = Vsta[(2 * np) * 130 + v];
                float y = Vsta[(2 * np + 1) * 130 + v];
                unsigned h, lo;
                splitpack2(x, y, h, lo);
                Vh32[v * 36 + np] = h;
                Vl32[v * 36 + np] = lo;
            }
        }
        __syncthreads();

        // ---- prefetch next chunk's raw K/V (overlaps with MMA below) ----
        if (c < NCHUNKS - 1) {
            int n1 = nblk + (c + 1) * CHUNK;
            const char* ksrc = (const char*)(Kg + ((size_t)b * NV + n1) * KD);
            const char* vsrc = (const char*)(Vg + ((size_t)b * NV + n1) * VD);
#pragma unroll
            for (int i = 0; i < 8; i++) {
                int off = (tid + i * 256) * 16;
                cpa16(KstaU + off, ksrc + off);
            }
#pragma unroll
            for (int i = 0; i < 9; i++) {
                int idx = tid + i * 256;
                if (idx < 2080) cpa16(VstaU + idx * 16, vsrc + idx * 16);
            }
            asm volatile("cp.async.commit_group;" ::: "memory");
        }

        const float* keepc = keepAll + c * 64;

        // ---- QK: S = Q K^T (3-pass split bf16), warp tile 16q x 64n ----
        float accS[8][4];
#pragma unroll
        for (int i = 0; i < 8; i++) { accS[i][0] = accS[i][1] = accS[i][2] = accS[i][3] = 0.0f; }

#pragma unroll
        for (int ks = 0; ks < 8; ks++) {
            unsigned ah0, ah1, ah2, ah3, al0, al1, al2, al3;
            LDSM_X4(ah0, ah1, ah2, ah3, aH + ks * 32);
            LDSM_X4(al0, al1, al2, al3, aL + ks * 32);
#pragma unroll
            for (int ntp = 0; ntp < 4; ntp++) {
                unsigned h0, h1, h2, h3, q0, q1, q2, q3;
                LDSM_X4(h0, h1, h2, h3, bKh + ntp * 4352 + ks * 32);
                LDSM_X4(q0, q1, q2, q3, bKl + ntp * 4352 + ks * 32);
                MMA4(accS[2 * ntp], ah0, ah1, ah2, ah3, h0, h1);
                MMA4(accS[2 * ntp], al0, al1, al2, al3, h0, h1);
                MMA4(accS[2 * ntp], ah0, ah1, ah2, ah3, q0, q1);
                MMA4(accS[2 * ntp + 1], ah0, ah1, ah2, ah3, h2, h3);
                MMA4(accS[2 * ntp + 1], al0, al1, al2, al3, h2, h3);
                MMA4(accS[2 * ntp + 1], ah0, ah1, ah2, ah3, q2, q3);
            }
        }

        // ---- epilogue in registers: P = exp2(S)*keep, re-split to bf16 ----
        unsigned phA[8], phB[8], plA[8], plB[8];
#pragma unroll
        for (int nt = 0; nt < 8; nt++) {
            int c0 = nt * 8 + 2 * t;
            float k0f = keepc[c0], k1f = keepc[c0 + 1];
            float p0 = exp2f(accS[nt][0]) * k0f;
            float p1 = exp2f(accS[nt][1]) * k1f;
            float p2 = exp2f(accS[nt][2]) * k0f;
            float p3 = exp2f(accS[nt][3]) * k1f;
            splitpack2(p0, p1, phA[nt], plA[nt]);
            splitpack2(p2, p3, phB[nt], plB[nt]);
        }

        // ---- PV: O += P @ [V|1]^T, warp tile 16q x 136v ----
#pragma unroll
        for (int ks = 0; ks < 4; ks++) {
            unsigned ah0 = phA[2 * ks], ah1 = phB[2 * ks];
            unsigned ah2 = phA[2 * ks + 1], ah3 = phB[2 * ks + 1];
            unsigned al0 = plA[2 * ks], al1 = plB[2 * ks];
            unsigned al2 = plA[2 * ks + 1], al3 = plB[2 * ks + 1];
#pragma unroll
            for (int vtp = 0; vtp < 8; vtp++) {
                unsigned h0, h1, h2, h3, q0, q1, q2, q3;
                LDSM_X4(h0, h1, h2, h3, bVh + vtp * 2304 + ks * 32);
                LDSM_X4(q0, q1, q2, q3, bVl + vtp * 2304 + ks * 32);
                MMA4(accO[2 * vtp], ah0, ah1, ah2, ah3, h0, h1);
                MMA4(accO[2 * vtp], al0, al1, al2, al3, h0, h1);
                MMA4(accO[2 * vtp], ah0, ah1, ah2, ah3, q0, q1);
                MMA4(accO[2 * vtp + 1], ah0, ah1, ah2, ah3, h2, h3);
                MMA4(accO[2 * vtp + 1], al0, al1, al2, al3, h2, h3);
                MMA4(accO[2 * vtp + 1], ah0, ah1, ah2, ah3, q2, q3);
            }
            { // tail tile v = 128..135 (includes ones column @130)
                unsigned h0, h1, q0, q1;
                LDSM_X2(h0, h1, bV2h + ks * 32);
                LDSM_X2(q0, q1, bV2l + ks * 32);
                MMA4(accO[16], ah0, ah1, ah2, ah3, h0, h1);
                MMA4(accO[16], al0, al1, al2, al3, h0, h1);
                MMA4(accO[16], ah0, ah1, ah2, ah3, q0, q1);
            }
        }
    }

    // write O tile to this split's obuf slot
    float* orow0 = g_obuf2 + (((size_t)split * BB + b) * QROWS + m0 + g) * OST;
    float* orow1 = orow0 + 8 * OST;
#pragma unroll
    for (int vt = 0; vt < 17; vt++) {
        int v0 = vt * 8 + 2 * t;
        *(float2*)(orow0 + v0) = make_float2(accO[vt][0], accO[vt][1]);
        *(float2*)(orow1 + v0) = make_float2(accO[vt][2], accO[vt][3]);
    }
}

// ---------------- kernel C: coalesced slot-reduce + normalize + MLP --------
__global__ void __launch_bounds__(128) mlp_kernel(
    const float* __restrict__ W3, const float* __restrict__ b3,
    const float* __restrict__ W4, const float* __restrict__ b4,
    const float* __restrict__ W5, const float* __restrict__ b5,
    float* __restrict__ out) {
    __shared__ float os2[544];
    __shared__ float os[520];
    __shared__ float h1[64];
    __shared__ float h2[32];
    int bid = blockIdx.x;            // b*32 + j
    int b = bid >> 5, j = bid & 31;
    int tid = threadIdx.x;           // 128
    const size_t slot = (size_t)BB * QROWS * OST;
    size_t base = ((size_t)b * QROWS + j * 4) * OST;
#pragma unroll
    for (int r = 0; r < 5; r++) {
        int idx = tid + r * 128;
        if (idx < 544) {
            float s = 0.0f;
#pragma unroll
            for (int sp = 0; sp < NSPLIT; sp++) s += g_obuf2[sp * slot + base + idx];
            os2[idx] = s;
        }
    }
    __syncthreads();
#pragma unroll
    for (int r = 0; r < 5; r++) {
        int idx = tid + r * 128;
        if (idx < 520) {
            int h = idx / 130, v = idx - h * 130;
            os[idx] = os2[h * 136 + v] / os2[h * 136 + 130];
        }
    }
    __syncthreads();
    if (tid < 64) {
        float s = b3[tid];
        for (int r = 0; r < 520; r++) s += os[r] * W3[r * 64 + tid];
        h1[tid] = fmaxf(s, 0.0f);
    }
    __syncthreads();
    if (tid < 32) {
        float s = b4[tid];
#pragma unroll
        for (int r = 0; r < 64; r++) s += h1[r] * W4[r * 32 + tid];
        h2[tid] = fmaxf(s, 0.0f);
    }
    __syncthreads();
    if (tid < 32) {
        float v = h2[tid] * W5[tid];
#pragma unroll
        for (int off = 16; off; off >>= 1) v += __shfl_down_sync(0xffffffffu, v, off);
        if (tid == 0) out[bid] = v + b5[0];
    }
}

// ---------------- launch ----------------------------------------------------
extern "C" void kernel_launch(void* const* d_in, const int* in_sizes, int n_in,
                              void* d_out, int out_size) {
    const float* jq = (const float*)d_in[0];
    const float* Kg = (const float*)d_in[1];
    const float* Vg = (const float*)d_in[2];
    const void*  mk = d_in[3];
    const float* W1 = (const float*)d_in[4];
    const float* b1 = (const float*)d_in[5];
    const float* W2 = (const float*)d_in[6];
    const float* b2 = (const float*)d_in[7];
    const float* W3 = (const float*)d_in[8];
    const float* b3 = (const float*)d_in[9];
    const float* W4 = (const float*)d_in[10];
    const float* b4 = (const float*)d_in[11];
    const float* W5 = (const float*)d_in[12];
    const float* b5 = (const float*)d_in[13];
    float* out = (float*)d_out;

    zero_flags<<<1, 32>>>();
    classify_mask<<<64, 256>>>((const uint4*)mk);
    convert_mask<<<(BB * NV + 255) / 256, 256>>>(mk, BB * NV);
    encoder_kernel<<<BB * JJ, 128>>>(jq, W1, b1, W2, b2);

    cudaFuncSetAttribute(fused_attn_kernel,
                         cudaFuncAttributeMaxDynamicSharedMemorySize, SM_TOTAL);
    dim3 g1(NSPLIT, BB);
    fused_attn_kernel<<<g1, 256, SM_TOTAL>>>(Kg, Vg);

    mlp_kernel<<<BB * JJ, 128>>>(W3, b3, W4, b4, W5, b5, out);
}